// round 9
// baseline (speedup 1.0000x reference)
#include <cuda_runtime.h>
#include <cuda_fp16.h>
#include <cstdint>
#include <math.h>

// ---------------------------------------------------------------------------
// Problem constants
// ---------------------------------------------------------------------------
#define H     128        // MEM_DIM
#define MSG   256        // MSG_DIM
#define BM    32         // rows per CTA (B=200000 = 6250*32)
#define BKH   32         // K halves per chunk
#define NCH   12         // 8 chunks X (K=256) + 4 chunks H (K=128)
#define NTHREADS 256
#define RSTR  40         // smem row stride in halves (80B, conflict-free ldmatrix)

// smem half-index offsets
#define SA0   0                    // 32 x 40
#define SA1   1280
#define SB0   2560                 // 3 stages of 384 x 40
#define BSTG  15360
// byte offsets
#define NODES_BYTE  97280          // 32 ints
#define BRZ_BYTE    97408          // 256 f32
#define BIN_BYTE    98432          // 128 f32
#define BHN_BYTE    98944          // 128 f32
#define SMEM_BYTES  99456

// fp16 weight scratch
__device__ half g_Wih_h[384 * MSG];
__device__ half g_Whh_h[384 * H];

__device__ __forceinline__ void ldsm_x4(uint32_t* r, uint32_t addr) {
    asm volatile("ldmatrix.sync.aligned.m8n8.x4.shared.b16 {%0,%1,%2,%3}, [%4];"
                 : "=r"(r[0]), "=r"(r[1]), "=r"(r[2]), "=r"(r[3]) : "r"(addr));
}
// NOTE: non-volatile on purpose — pure register op, lets ptxas software-pipeline
__device__ __forceinline__ void mma_f16(float* d, const uint32_t* a,
                                        uint32_t b0, uint32_t b1) {
    asm("mma.sync.aligned.m16n8k16.row.col.f32.f16.f16.f32 "
        "{%0,%1,%2,%3}, {%4,%5,%6,%7}, {%8,%9}, {%0,%1,%2,%3};"
        : "+f"(d[0]), "+f"(d[1]), "+f"(d[2]), "+f"(d[3])
        : "r"(a[0]), "r"(a[1]), "r"(a[2]), "r"(a[3]), "r"(b0), "r"(b1));
}
__device__ __forceinline__ uint32_t pack_h2(float x, float y) {
    half2 h = __float22half2_rn(make_float2(x, y));
    return *(uint32_t*)&h;
}
__device__ __forceinline__ void cp16(uint32_t smem_addr, const void* gptr) {
    asm volatile("cp.async.ca.shared.global [%0], [%1], 16;"
                 :: "r"(smem_addr), "l"(gptr) : "memory");
}
#define CP_COMMIT() asm volatile("cp.async.commit_group;" ::: "memory")
#define CP_WAIT1()  asm volatile("cp.async.wait_group 1;" ::: "memory")
#define CP_WAIT0()  asm volatile("cp.async.wait_group 0;" ::: "memory")

// ---------------------------------------------------------------------------
// Prep: convert weights to fp16 scratch
// ---------------------------------------------------------------------------
__global__ void prep_kernel(const float* __restrict__ W_ih,
                            const float* __restrict__ W_hh) {
    int i = blockIdx.x * blockDim.x + threadIdx.x;
    int stride = gridDim.x * blockDim.x;
    for (int j = i; j < 384 * MSG + 384 * H; j += stride) {
        if (j < 384 * MSG) g_Wih_h[j] = __float2half_rn(W_ih[j]);
        else               g_Whh_h[j - 384 * MSG] = __float2half_rn(W_hh[j - 384 * MSG]);
    }
}

// ---------------------------------------------------------------------------
// Bulk clone: memory + last_update -> out (single launch, 85% DRAM)
// ---------------------------------------------------------------------------
__global__ void clone_kernel(const float4* __restrict__ mem_src,
                             float4* __restrict__ mem_dst, long n4m,
                             const float4* __restrict__ lu_src,
                             float4* __restrict__ lu_dst, long n4l) {
    long i = (long)blockIdx.x * blockDim.x + threadIdx.x;
    long stride = (long)gridDim.x * blockDim.x;
    for (long j = i; j < n4m; j += stride) mem_dst[j] = mem_src[j];
    for (long j = i; j < n4l; j += stride) lu_dst[j] = lu_src[j];
}

// ---------------------------------------------------------------------------
// GRU update (fp16 mma) + scatter. 256 threads, 2 CTAs/SM.
// 8 warps: wn = wid (0..7) -> 16-col group in each of the 3 gates; all warps
// cover the full 32-row slab (2 m16 tiles).
// ---------------------------------------------------------------------------
__global__ __launch_bounds__(NTHREADS, 2)
void gru_mma_kernel(const float* __restrict__ memory,
                    const int*   __restrict__ node_ids,
                    const float* __restrict__ X,
                    const float* __restrict__ ts,
                    const float* __restrict__ b_ih,
                    const float* __restrict__ b_hh,
                    float* __restrict__ out_mem,
                    float* __restrict__ out_lu,
                    int B)
{
    extern __shared__ char smc[];
    half*  smh     = (half*)smc;
    int*   s_nodes = (int*)  (smc + NODES_BYTE);
    float* s_brz   = (float*)(smc + BRZ_BYTE);
    float* s_bin   = (float*)(smc + BIN_BYTE);
    float* s_bhn   = (float*)(smc + BHN_BYTE);
    const uint32_t sh_base = (uint32_t)__cvta_generic_to_shared(smc);

    const int tid  = threadIdx.x;
    const int lane = tid & 31;
    const int wn   = tid >> 5;          // warp id = N-group
    const int gid  = lane >> 2;
    const int tig  = lane & 3;
    const int row0 = blockIdx.x * BM;

    if (tid < BM) {
        int r = row0 + tid;
        s_nodes[tid] = node_ids[r < B ? r : (B - 1)];
    }
    s_brz[tid] = b_ih[tid] + b_hh[tid];                 // 256 threads cover 256
    if (tid < 128) s_bin[tid] = b_ih[256 + tid];
    else           s_bhn[tid - 128] = b_hh[256 + (tid - 128)];
    __syncthreads();

    // ---- B fill via cp.async: 1536 x 16B per chunk, 6 per thread ----
    const int b_r = tid >> 2, b_q = tid & 3;            // r base 0..63, q 0..3
    auto fill_B = [&](int stage, int c) {
        const uint32_t dst0 = sh_base + (uint32_t)(SB0 + stage * BSTG) * 2u;
        if (c < 8) {
            const half* src = g_Wih_h + c * BKH;
            #pragma unroll
            for (int i = 0; i < 6; i++) {
                int r = b_r + i * 64;
                cp16(dst0 + (uint32_t)(r * RSTR + b_q * 8) * 2u,
                     src + (long)r * MSG + b_q * 8);
            }
        } else {
            const half* src = g_Whh_h + (c - 8) * BKH;
            #pragma unroll
            for (int i = 0; i < 6; i++) {
                int r = b_r + i * 64;
                cp16(dst0 + (uint32_t)(r * RSTR + b_q * 8) * 2u,
                     src + (long)r * H + b_q * 8);
            }
        }
    };

    // ---- A fill: 1 float4/thread (32 rows x 8 quads), register double-buffer
    const int a_r = tid >> 3, a_q = tid & 7;
    auto load_A = [&](int c) -> float4 {
        if (c < 8) {
            int gr = row0 + a_r; if (gr >= B) gr = B - 1;
            return *(const float4*)(X + (long)gr * MSG + c * BKH + a_q * 4);
        } else {
            int node = s_nodes[a_r];
            return *(const float4*)(memory + (long)node * H + (c - 8) * BKH + a_q * 4);
        }
    };
    auto store_A = [&](int s, float4 v) {
        half* sA = smh + (s ? SA1 : SA0);
        *(uint2*)(sA + a_r * RSTR + a_q * 4) =
            make_uint2(pack_h2(v.x, v.y), pack_h2(v.z, v.w));
    };

    // accumulators: [m16 tile][0,1=r 2,3=z 4,5=i_n 6,7=h_n][frag]
    float acc[2][8][4];
    #pragma unroll
    for (int t = 0; t < 2; t++)
        #pragma unroll
        for (int g = 0; g < 8; g++)
            #pragma unroll
            for (int j = 0; j < 4; j++) acc[t][g][j] = 0.f;

    // ---- prologue ----
    fill_B(0, 0); CP_COMMIT();
    fill_B(1, 1); CP_COMMIT();
    float4 pa = load_A(0);
    store_A(0, pa);
    pa = load_A(1);

    const int lr = lane & 15;
    const int lk = (lane >> 4) * 8;

    for (int c = 0; c < NCH; c++) {
        if (c + 1 < NCH) CP_WAIT1(); else CP_WAIT0();
        __syncthreads();                       // stage (c+2)%3 free, chunk c ready

        if (c + 2 < NCH) { fill_B((c + 2) % 3, c + 2); CP_COMMIT(); }
        if (c + 1 < NCH) {
            store_A((c + 1) & 1, pa);
            if (c + 2 < NCH) pa = load_A(c + 2);
        }

        const uint32_t baseA = sh_base + (uint32_t)((c & 1) ? SA1 : SA0) * 2u;
        const uint32_t baseB = sh_base + (uint32_t)(SB0 + (c % 3) * BSTG) * 2u;
        const int nb = (c < 8) ? 4 : 6;

        #pragma unroll
        for (int kk = 0; kk < 2; kk++) {
            const uint32_t kof = (uint32_t)(kk * 16 + lk) * 2u;
            uint32_t a[2][4], br[4], bz[4], bn[4];
            ldsm_x4(a[0], baseA + (uint32_t)( 0 + lr) * (RSTR * 2u) + kof);
            ldsm_x4(a[1], baseA + (uint32_t)(16 + lr) * (RSTR * 2u) + kof);
            ldsm_x4(br,   baseB + (uint32_t)(      wn * 16 + lr) * (RSTR * 2u) + kof);
            ldsm_x4(bz,   baseB + (uint32_t)(128 + wn * 16 + lr) * (RSTR * 2u) + kof);
            ldsm_x4(bn,   baseB + (uint32_t)(256 + wn * 16 + lr) * (RSTR * 2u) + kof);
            #pragma unroll
            for (int t = 0; t < 2; t++) {
                mma_f16(acc[t][0],      a[t], br[0], br[2]);
                mma_f16(acc[t][1],      a[t], br[1], br[3]);
                mma_f16(acc[t][2],      a[t], bz[0], bz[2]);
                mma_f16(acc[t][3],      a[t], bz[1], bz[3]);
                mma_f16(acc[t][nb],     a[t], bn[0], bn[2]);
                mma_f16(acc[t][nb + 1], a[t], bn[1], bn[3]);
            }
        }
    }

    // ---- register-local epilogue: gates + scatter ----
    #pragma unroll
    for (int t = 0; t < 2; t++) {
        #pragma unroll
        for (int s = 0; s < 2; s++) {
            const int r_local = t * 16 + gid + s * 8;
            const int grow = row0 + r_local;
            if (grow < B) {
                const int node = s_nodes[r_local];
                #pragma unroll
                for (int nt = 0; nt < 2; nt++) {
                    const int c0 = wn * 16 + nt * 8 + tig * 2;
                    float2 hv = *(const float2*)(memory + (long)node * H + c0);
                    float hh[2] = {hv.x, hv.y};
                    float o[2];
                    #pragma unroll
                    for (int j = 0; j < 2; j++) {
                        const int fi = s * 2 + j;
                        float rg = 1.0f / (1.0f + __expf(-(acc[t][nt][fi]     + s_brz[c0 + j])));
                        float zg = 1.0f / (1.0f + __expf(-(acc[t][2 + nt][fi] + s_brz[128 + c0 + j])));
                        float ng = tanhf(acc[t][4 + nt][fi] + s_bin[c0 + j]
                                         + rg * (acc[t][6 + nt][fi] + s_bhn[c0 + j]));
                        o[j] = (1.0f - zg) * ng + zg * hh[j];
                    }
                    *(float2*)(out_mem + (long)node * H + c0) = make_float2(o[0], o[1]);
                }
            }
        }
    }
    if (tid < BM) {
        int r = row0 + tid;
        if (r < B) out_lu[s_nodes[tid]] = ts[r];
    }
}

// ---------------------------------------------------------------------------
// Launch. Inputs (metadata order):
//   0 memory [N,128] | 1 last_update [N] | 2 unique_node_ids [B] i32
//   3 unique_messages [B,256] | 4 timestamps [B]
//   5 W_ih [384,256] | 6 W_hh [384,128] | 7 b_ih [384] | 8 b_hh [384]
// Output: concat(updated_memory [N*128], updated_last_update [N]) f32
// ---------------------------------------------------------------------------
extern "C" void kernel_launch(void* const* d_in, const int* in_sizes, int n_in,
                              void* d_out, int out_size) {
    const float* memory      = (const float*)d_in[0];
    const float* last_update = (const float*)d_in[1];
    const int*   node_ids    = (const int*)  d_in[2];
    const float* X           = (const float*)d_in[3];
    const float* ts          = (const float*)d_in[4];
    const float* W_ih        = (const float*)d_in[5];
    const float* W_hh        = (const float*)d_in[6];
    const float* b_ih        = (const float*)d_in[7];
    const float* b_hh        = (const float*)d_in[8];

    const int n_nodes = in_sizes[1];
    const int B       = in_sizes[2];

    float* out_mem = (float*)d_out;
    float* out_lu  = out_mem + (long)n_nodes * H;

    // 1) fp16 weight conversion (tiny)
    prep_kernel<<<288, 512>>>(W_ih, W_hh);
    // 2) full clone (near-DRAM-roofline)
    {
        long n4m = (long)n_nodes * H / 4;
        long n4l = (long)n_nodes / 4;
        clone_kernel<<<16384, 256>>>((const float4*)memory, (float4*)out_mem, n4m,
                                     (const float4*)last_update, (float4*)out_lu, n4l);
    }
    // 3) GRU + scatter (overwrites updated rows)
    {
        cudaFuncSetAttribute(gru_mma_kernel,
                             cudaFuncAttributeMaxDynamicSharedMemorySize, SMEM_BYTES);
        int blocks = (B + BM - 1) / BM;
        gru_mma_kernel<<<blocks, NTHREADS, SMEM_BYTES>>>(memory, node_ids, X, ts,
                                                         b_ih, b_hh,
                                                         out_mem, out_lu, B);
    }
}

// round 10
// speedup vs baseline: 1.3827x; 1.3827x over previous
#include <cuda_runtime.h>
#include <cuda_fp16.h>
#include <cstdint>
#include <math.h>

// ---------------------------------------------------------------------------
// Problem constants
// ---------------------------------------------------------------------------
#define H     128        // MEM_DIM
#define MSG   256        // MSG_DIM
#define KTOT  384        // fused K = MSG + H
#define TM    32         // rows per tile
#define NPAIRS 148       // tile stride (CTAs per column-half)
#define NTHREADS 256
#define WST   392        // smem row stride in halves (784B; 49x16B -> conflict-free)
#define WSTB  784

#define SLAB_ROWS 192                        // 3 gates x 64 cols (one column half)
#define A0_BYTE   (SLAB_ROWS * WSTB)         // 150528
#define ASTG_BYTE (TM * WSTB)                // 25088
#define SMEM_BYTES (A0_BYTE + 2 * ASTG_BYTE) // 200704

// fp16 weight scratch
__device__ half g_Wih_h[384 * MSG];
__device__ half g_Whh_h[384 * H];

__device__ __forceinline__ void ldsm_x4(uint32_t* r, uint32_t addr) {
    asm volatile("ldmatrix.sync.aligned.m8n8.x4.shared.b16 {%0,%1,%2,%3}, [%4];"
                 : "=r"(r[0]), "=r"(r[1]), "=r"(r[2]), "=r"(r[3]) : "r"(addr));
}
// non-volatile: pure register op, lets ptxas schedule freely
__device__ __forceinline__ void mma_f16(float* d, const uint32_t* a,
                                        uint32_t b0, uint32_t b1) {
    asm("mma.sync.aligned.m16n8k16.row.col.f32.f16.f16.f32 "
        "{%0,%1,%2,%3}, {%4,%5,%6,%7}, {%8,%9}, {%0,%1,%2,%3};"
        : "+f"(d[0]), "+f"(d[1]), "+f"(d[2]), "+f"(d[3])
        : "r"(a[0]), "r"(a[1]), "r"(a[2]), "r"(a[3]), "r"(b0), "r"(b1));
}
__device__ __forceinline__ uint32_t pack_h2(float x, float y) {
    half2 h = __float22half2_rn(make_float2(x, y));
    return *(uint32_t*)&h;
}
__device__ __forceinline__ void cp16(uint32_t smem_addr, const void* gptr) {
    asm volatile("cp.async.ca.shared.global [%0], [%1], 16;"
                 :: "r"(smem_addr), "l"(gptr) : "memory");
}
#define CP_COMMIT() asm volatile("cp.async.commit_group;" ::: "memory")
#define CP_WAIT0()  asm volatile("cp.async.wait_group 0;" ::: "memory")

// ---------------------------------------------------------------------------
// Prep: convert weights to fp16 scratch
// ---------------------------------------------------------------------------
__global__ void prep_kernel(const float* __restrict__ W_ih,
                            const float* __restrict__ W_hh) {
    int i = blockIdx.x * blockDim.x + threadIdx.x;
    int stride = gridDim.x * blockDim.x;
    for (int j = i; j < 384 * MSG + 384 * H; j += stride) {
        if (j < 384 * MSG) g_Wih_h[j] = __float2half_rn(W_ih[j]);
        else               g_Whh_h[j - 384 * MSG] = __float2half_rn(W_hh[j - 384 * MSG]);
    }
}

// ---------------------------------------------------------------------------
// Bulk clone: memory + last_update -> out
// ---------------------------------------------------------------------------
__global__ void clone_kernel(const float4* __restrict__ mem_src,
                             float4* __restrict__ mem_dst, long n4m,
                             const float4* __restrict__ lu_src,
                             float4* __restrict__ lu_dst, long n4l) {
    long i = (long)blockIdx.x * blockDim.x + threadIdx.x;
    long stride = (long)gridDim.x * blockDim.x;
    for (long j = i; j < n4m; j += stride) mem_dst[j] = mem_src[j];
    for (long j = i; j < n4l; j += stride) lu_dst[j] = lu_src[j];
}

// ---------------------------------------------------------------------------
// Weight-resident persistent GRU kernel.
// grid = 2*NPAIRS. ch = bid&1 -> gate-column half [ch*64, ch*64+64).
// Weight slab (192 rows x 384 K halves) loaded ONCE; then ~42 row-tiles of 32
// with a barrier-free K loop and double-buffered A stage.
// ---------------------------------------------------------------------------
__global__ __launch_bounds__(NTHREADS, 1)
void gru_persist_kernel(const float* __restrict__ memory,
                        const int*   __restrict__ node_ids,
                        const float* __restrict__ X,
                        const float* __restrict__ ts,
                        const float* __restrict__ b_ih,
                        const float* __restrict__ b_hh,
                        float* __restrict__ out_mem,
                        float* __restrict__ out_lu,
                        int B, int ntiles)
{
    extern __shared__ char smc[];
    half* smh = (half*)smc;
    const uint32_t sh_base = (uint32_t)__cvta_generic_to_shared(smc);

    const int tid  = threadIdx.x;
    const int lane = tid & 31;
    const int wn   = tid >> 5;            // warp -> 8-col group within the half
    const int gid  = lane >> 2;
    const int tig  = lane & 3;
    const int ch   = blockIdx.x & 1;      // column half
    const int tstart = blockIdx.x >> 1;

    // per-thread bias registers (cols colb, colb+1 of each gate)
    const int colb = ch * 64 + wn * 8 + tig * 2;
    const float brz0 = b_ih[colb]       + b_hh[colb];
    const float brz1 = b_ih[colb + 1]   + b_hh[colb + 1];
    const float bzz0 = b_ih[128 + colb] + b_hh[128 + colb];
    const float bzz1 = b_ih[128 + colb + 1] + b_hh[128 + colb + 1];
    const float bin0 = b_ih[256 + colb],     bin1 = b_ih[256 + colb + 1];
    const float bhn0 = b_hh[256 + colb],     bhn1 = b_hh[256 + colb + 1];

    // ---- load weight slab once: 192 rows x (256 Wih + 128 Whh) halves ----
    // slab row n: gate g = n>>6, weight row = g*128 + ch*64 + (n&63)
    #pragma unroll
    for (int i = 0; i < 36; i++) {
        int idx = tid + i * NTHREADS;     // < 9216 16B-units
        int n = idx / 48, u = idx - n * 48;
        int wrow = ((n >> 6) << 7) + (ch << 6) + (n & 63);
        if (u < 32) {
            cp16(sh_base + (uint32_t)(n * WSTB + u * 16),
                 g_Wih_h + (long)wrow * MSG + u * 8);
        } else {
            cp16(sh_base + (uint32_t)(n * WSTB + 512 + (u - 32) * 16),
                 g_Whh_h + (long)wrow * H + (u - 32) * 8);
        }
    }

    // ---- A fill helpers ----
    // thread t: tile row = t>>3, quad base q0 = t&7; 12 f4 per thread.
    // logical K col = q*4: q<64 -> X, q>=64 -> gathered memory row.
    const int a_r = tid >> 3, q0 = tid & 7;

    auto fill_A_direct = [&](int tile, int stage) {
        long grow = (long)tile * TM + a_r; if (grow >= B) grow = B - 1;
        half* dst = smh + (A0_BYTE + stage * ASTG_BYTE) / 2 + a_r * WST;
        const float4* xs = (const float4*)(X + grow * MSG);
        #pragma unroll
        for (int j = 0; j < 8; j++) {
            int q = q0 + j * 8;
            float4 v = xs[q];
            *(uint2*)(dst + q * 4) = make_uint2(pack_h2(v.x, v.y), pack_h2(v.z, v.w));
        }
        int node = node_ids[grow];
        const float4* ms = (const float4*)(memory + (long)node * H);
        #pragma unroll
        for (int j = 0; j < 4; j++) {
            int q = q0 + 64 + j * 8;
            float4 v = ms[q - 64];
            *(uint2*)(dst + q * 4) = make_uint2(pack_h2(v.x, v.y), pack_h2(v.z, v.w));
        }
    };

    fill_A_direct(tstart, 0);
    CP_COMMIT();
    CP_WAIT0();
    __syncthreads();

    // ldsm base addresses
    const int lane8 = lane & 7, laneA = lane & 15;
    const uint32_t aOff = (uint32_t)laneA * WSTB + (uint32_t)(lane >> 4) * 16;
    const uint32_t bOff0 = sh_base + (uint32_t)((      wn * 8 + lane8) * WSTB) + (uint32_t)(lane >> 3) * 16;
    const uint32_t bOff1 = sh_base + (uint32_t)((64  + wn * 8 + lane8) * WSTB) + (uint32_t)(lane >> 3) * 16;
    const uint32_t bOff2 = sh_base + (uint32_t)((128 + wn * 8 + lane8) * WSTB) + (uint32_t)(lane >> 3) * 16;

    int s = 0;
    for (int tile = tstart; tile < ntiles; tile += NPAIRS) {
        const int next = tile + NPAIRS;
        const bool has_next = next < ntiles;

        // prefetch next A tile into registers
        float4 pa[12];
        if (has_next) {
            long grow = (long)next * TM + a_r; if (grow >= B) grow = B - 1;
            const float4* xs = (const float4*)(X + grow * MSG);
            #pragma unroll
            for (int j = 0; j < 8; j++) pa[j] = xs[q0 + j * 8];
            int node = node_ids[grow];
            const float4* ms = (const float4*)(memory + (long)node * H);
            #pragma unroll
            for (int j = 0; j < 4; j++) pa[8 + j] = ms[q0 + j * 8];
        }

        // accumulators: [m16 tile][0=r 1=z 2=i_n 3=h_n][frag]
        float acc[2][4][4];
        #pragma unroll
        for (int mt = 0; mt < 2; mt++)
            #pragma unroll
            for (int g = 0; g < 4; g++)
                #pragma unroll
                for (int j = 0; j < 4; j++) acc[mt][g][j] = 0.f;

        const uint32_t aB0 = sh_base + (uint32_t)(A0_BYTE + s * ASTG_BYTE) + aOff;
        const uint32_t aB1 = aB0 + 16u * WSTB;

        // ---- barrier-free K loop: 12 k32 steps ----
        #pragma unroll
        for (int c = 0; c < 12; c++) {
            const uint32_t ko = (uint32_t)c * 64u;
            uint32_t a[2][2][4], bb[3][4];
            ldsm_x4(a[0][0], aB0 + ko);
            ldsm_x4(a[0][1], aB0 + ko + 32);
            ldsm_x4(a[1][0], aB1 + ko);
            ldsm_x4(a[1][1], aB1 + ko + 32);
            ldsm_x4(bb[0], bOff0 + ko);
            ldsm_x4(bb[1], bOff1 + ko);
            ldsm_x4(bb[2], bOff2 + ko);
            const int ng = (c < 8) ? 2 : 3;   // i_n vs h_n bank
            #pragma unroll
            for (int mt = 0; mt < 2; mt++) {
                mma_f16(acc[mt][0],  a[mt][0], bb[0][0], bb[0][1]);
                mma_f16(acc[mt][0],  a[mt][1], bb[0][2], bb[0][3]);
                mma_f16(acc[mt][1],  a[mt][0], bb[1][0], bb[1][1]);
                mma_f16(acc[mt][1],  a[mt][1], bb[1][2], bb[1][3]);
                mma_f16(acc[mt][ng], a[mt][0], bb[2][0], bb[2][1]);
                mma_f16(acc[mt][ng], a[mt][1], bb[2][2], bb[2][3]);
            }
        }

        // store prefetched A into the other stage
        if (has_next) {
            half* dst = smh + (A0_BYTE + (s ^ 1) * ASTG_BYTE) / 2 + a_r * WST;
            #pragma unroll
            for (int j = 0; j < 12; j++) {
                int q = q0 + j * 8 + ((j >= 8) ? 64 - 64 : 0); // q0+j*8 (X), then +64 handled below
                (void)q;
            }
            #pragma unroll
            for (int j = 0; j < 8; j++) {
                int q = q0 + j * 8;
                *(uint2*)(dst + q * 4) =
                    make_uint2(pack_h2(pa[j].x, pa[j].y), pack_h2(pa[j].z, pa[j].w));
            }
            #pragma unroll
            for (int j = 0; j < 4; j++) {
                int q = q0 + 64 + j * 8;
                *(uint2*)(dst + q * 4) =
                    make_uint2(pack_h2(pa[8 + j].x, pa[8 + j].y), pack_h2(pa[8 + j].z, pa[8 + j].w));
            }
        }

        // ---- epilogue: gates + scatter (register-local) ----
        #pragma unroll
        for (int mt = 0; mt < 2; mt++) {
            #pragma unroll
            for (int sr = 0; sr < 2; sr++) {
                const int rloc = mt * 16 + gid + sr * 8;
                const long grow = (long)tile * TM + rloc;
                if (grow < B) {
                    const int node = node_ids[grow];
                    float2 hv = *(const float2*)(memory + (long)node * H + colb);
                    const int f = sr * 2;
                    float rg0 = 1.0f / (1.0f + __expf(-(acc[mt][0][f]     + brz0)));
                    float rg1 = 1.0f / (1.0f + __expf(-(acc[mt][0][f + 1] + brz1)));
                    float zg0 = 1.0f / (1.0f + __expf(-(acc[mt][1][f]     + bzz0)));
                    float zg1 = 1.0f / (1.0f + __expf(-(acc[mt][1][f + 1] + bzz1)));
                    float ng0 = tanhf(acc[mt][2][f]     + bin0 + rg0 * (acc[mt][3][f]     + bhn0));
                    float ng1 = tanhf(acc[mt][2][f + 1] + bin1 + rg1 * (acc[mt][3][f + 1] + bhn1));
                    float2 o = make_float2((1.0f - zg0) * ng0 + zg0 * hv.x,
                                           (1.0f - zg1) * ng1 + zg1 * hv.y);
                    *(float2*)(out_mem + (long)node * H + colb) = o;
                }
            }
        }
        if (ch == 0 && tid < TM) {
            long grow = (long)tile * TM + tid;
            if (grow < B) out_lu[node_ids[grow]] = ts[grow];
        }

        if (has_next) __syncthreads();   // all warps done with both stages' role swap
        s ^= 1;
    }
}

// ---------------------------------------------------------------------------
// Launch. Inputs (metadata order):
//   0 memory [N,128] | 1 last_update [N] | 2 unique_node_ids [B] i32
//   3 unique_messages [B,256] | 4 timestamps [B]
//   5 W_ih [384,256] | 6 W_hh [384,128] | 7 b_ih [384] | 8 b_hh [384]
// Output: concat(updated_memory [N*128], updated_last_update [N]) f32
// ---------------------------------------------------------------------------
extern "C" void kernel_launch(void* const* d_in, const int* in_sizes, int n_in,
                              void* d_out, int out_size) {
    const float* memory      = (const float*)d_in[0];
    const float* last_update = (const float*)d_in[1];
    const int*   node_ids    = (const int*)  d_in[2];
    const float* X           = (const float*)d_in[3];
    const float* ts          = (const float*)d_in[4];
    const float* W_ih        = (const float*)d_in[5];
    const float* W_hh        = (const float*)d_in[6];
    const float* b_ih        = (const float*)d_in[7];
    const float* b_hh        = (const float*)d_in[8];

    const int n_nodes = in_sizes[1];
    const int B       = in_sizes[2];

    float* out_mem = (float*)d_out;
    float* out_lu  = out_mem + (long)n_nodes * H;

    // 1) fp16 weight conversion
    prep_kernel<<<288, 512>>>(W_ih, W_hh);
    // 2) full clone (near-DRAM-roofline)
    {
        long n4m = (long)n_nodes * H / 4;
        long n4l = (long)n_nodes / 4;
        clone_kernel<<<16384, 256>>>((const float4*)memory, (float4*)out_mem, n4m,
                                     (const float4*)last_update, (float4*)out_lu, n4l);
    }
    // 3) weight-resident persistent GRU (overwrites updated rows)
    {
        cudaFuncSetAttribute(gru_persist_kernel,
                             cudaFuncAttributeMaxDynamicSharedMemorySize, SMEM_BYTES);
        int ntiles = (B + TM - 1) / TM;
        gru_persist_kernel<<<2 * NPAIRS, NTHREADS, SMEM_BYTES>>>(
            memory, node_ids, X, ts, b_ih, b_hh, out_mem, out_lu, B, ntiles);
    }
}